// round 1
// baseline (speedup 1.0000x reference)
#include <cuda_runtime.h>

// NormalizedCrossCorrelation via Parseval identity:
//   Ex = DT * sum(x^2) + EPS   (since sum_k|X_k|^2 = nt * sum_n x_n^2)
//   cc = sum(x*y) / sqrt(Ex*Ey), masked by max|x|>0, summed over columns.
//
// Layout: x,y are [nt=4096, ncol=3072] row-major (columns contiguous).
// Pass 1: grid (6, 128). Each block: 128 threads x float4 (=512 cols) x 32 time rows.
//         Writes per-(split, col4) partial stats to __device__ scratch.
// Pass 2: grid (6). Each thread reduces 128 partials for its 4 columns,
//         computes cc, block-reduces, atomicAdd into the scalar output.

#define NT              4096
#define NCOL            3072
#define NC4             768          // NCOL / 4
#define SPLITS          128
#define ROWS_PER_SPLIT  32           // NT / SPLITS
#define BLK             128
#define COL_BLOCKS      6            // NC4 / BLK
#define DT_CONST        0.001f
#define EPS_CONST       1e-10f

__device__ float4 g_sx2[SPLITS * NC4];
__device__ float4 g_sy2[SPLITS * NC4];
__device__ float4 g_sxy[SPLITS * NC4];
__device__ float4 g_mx [SPLITS * NC4];

__global__ void ncc_zero(float* __restrict__ out) {
    if (threadIdx.x == 0) out[0] = 0.0f;
}

__global__ __launch_bounds__(BLK) void ncc_pass1(const float4* __restrict__ x,
                                                 const float4* __restrict__ y) {
    const int col4 = blockIdx.x * BLK + threadIdx.x;      // 0..767
    const int row0 = blockIdx.y * ROWS_PER_SPLIT;

    float4 sx2 = make_float4(0.f, 0.f, 0.f, 0.f);
    float4 sy2 = make_float4(0.f, 0.f, 0.f, 0.f);
    float4 sxy = make_float4(0.f, 0.f, 0.f, 0.f);
    float4 mx  = make_float4(0.f, 0.f, 0.f, 0.f);

    const float4* xp = x + (size_t)row0 * NC4 + col4;
    const float4* yp = y + (size_t)row0 * NC4 + col4;

#pragma unroll 8
    for (int r = 0; r < ROWS_PER_SPLIT; r++) {
        const float4 xv = __ldcs(xp);
        const float4 yv = __ldcs(yp);
        xp += NC4; yp += NC4;

        sx2.x = fmaf(xv.x, xv.x, sx2.x);
        sx2.y = fmaf(xv.y, xv.y, sx2.y);
        sx2.z = fmaf(xv.z, xv.z, sx2.z);
        sx2.w = fmaf(xv.w, xv.w, sx2.w);

        sy2.x = fmaf(yv.x, yv.x, sy2.x);
        sy2.y = fmaf(yv.y, yv.y, sy2.y);
        sy2.z = fmaf(yv.z, yv.z, sy2.z);
        sy2.w = fmaf(yv.w, yv.w, sy2.w);

        sxy.x = fmaf(xv.x, yv.x, sxy.x);
        sxy.y = fmaf(xv.y, yv.y, sxy.y);
        sxy.z = fmaf(xv.z, yv.z, sxy.z);
        sxy.w = fmaf(xv.w, yv.w, sxy.w);

        mx.x = fmaxf(mx.x, fabsf(xv.x));
        mx.y = fmaxf(mx.y, fabsf(xv.y));
        mx.z = fmaxf(mx.z, fabsf(xv.z));
        mx.w = fmaxf(mx.w, fabsf(xv.w));
    }

    const int o = blockIdx.y * NC4 + col4;
    g_sx2[o] = sx2;
    g_sy2[o] = sy2;
    g_sxy[o] = sxy;
    g_mx [o] = mx;
}

__global__ __launch_bounds__(BLK) void ncc_pass2(float* __restrict__ out) {
    const int col4 = blockIdx.x * BLK + threadIdx.x;      // 0..767

    float4 sx2 = make_float4(0.f, 0.f, 0.f, 0.f);
    float4 sy2 = make_float4(0.f, 0.f, 0.f, 0.f);
    float4 sxy = make_float4(0.f, 0.f, 0.f, 0.f);
    float4 mx  = make_float4(0.f, 0.f, 0.f, 0.f);

#pragma unroll 4
    for (int s = 0; s < SPLITS; s++) {
        const int o = s * NC4 + col4;
        const float4 a = g_sx2[o];
        const float4 b = g_sy2[o];
        const float4 c = g_sxy[o];
        const float4 m = g_mx [o];
        sx2.x += a.x; sx2.y += a.y; sx2.z += a.z; sx2.w += a.w;
        sy2.x += b.x; sy2.y += b.y; sy2.z += b.z; sy2.w += b.w;
        sxy.x += c.x; sxy.y += c.y; sxy.z += c.z; sxy.w += c.w;
        mx.x = fmaxf(mx.x, m.x); mx.y = fmaxf(mx.y, m.y);
        mx.z = fmaxf(mx.z, m.z); mx.w = fmaxf(mx.w, m.w);
    }

    float acc = 0.0f;
    {
        const float ex = DT_CONST * sx2.x + EPS_CONST;
        const float ey = DT_CONST * sy2.x + EPS_CONST;
        if (mx.x > 0.f) acc += sxy.x / sqrtf(ex * ey);
    }
    {
        const float ex = DT_CONST * sx2.y + EPS_CONST;
        const float ey = DT_CONST * sy2.y + EPS_CONST;
        if (mx.y > 0.f) acc += sxy.y / sqrtf(ex * ey);
    }
    {
        const float ex = DT_CONST * sx2.z + EPS_CONST;
        const float ey = DT_CONST * sy2.z + EPS_CONST;
        if (mx.z > 0.f) acc += sxy.z / sqrtf(ex * ey);
    }
    {
        const float ex = DT_CONST * sx2.w + EPS_CONST;
        const float ey = DT_CONST * sy2.w + EPS_CONST;
        if (mx.w > 0.f) acc += sxy.w / sqrtf(ex * ey);
    }

    // warp reduce
#pragma unroll
    for (int off = 16; off > 0; off >>= 1)
        acc += __shfl_down_sync(0xFFFFFFFFu, acc, off);

    __shared__ float warp_sums[BLK / 32];
    const int lane = threadIdx.x & 31;
    const int wid  = threadIdx.x >> 5;
    if (lane == 0) warp_sums[wid] = acc;
    __syncthreads();

    if (wid == 0) {
        float v = (lane < BLK / 32) ? warp_sums[lane] : 0.0f;
#pragma unroll
        for (int off = 2; off > 0; off >>= 1)
            v += __shfl_down_sync(0xFFFFFFFFu, v, off);
        if (lane == 0) atomicAdd(out, v);
    }
}

extern "C" void kernel_launch(void* const* d_in, const int* in_sizes, int n_in,
                              void* d_out, int out_size) {
    const float4* x = (const float4*)d_in[0];
    const float4* y = (const float4*)d_in[1];
    float* out = (float*)d_out;

    ncc_zero<<<1, 32>>>(out);
    ncc_pass1<<<dim3(COL_BLOCKS, SPLITS), BLK>>>(x, y);
    ncc_pass2<<<COL_BLOCKS, BLK>>>(out);
}

// round 3
// speedup vs baseline: 1.5766x; 1.5766x over previous
#include <cuda_runtime.h>

// NormalizedCrossCorrelation via Parseval identity:
//   sum_k |X_k|^2 = nt * sum_n x_n^2  =>  Ex = DT * sum(x^2) + EPS
//   cc = sum(x*y) / sqrt(Ex*Ey), masked by max|x|>0, summed over all columns.
//
// x,y: [nt=4096, ncol=3072] row-major (columns contiguous).
// pass1: grid (6, 64), 128 threads. Thread owns one float4 column-group for 64
//        rows, with explicit double-buffered loads (8 LDG.128 in flight).
//        Block (0,0) also zeroes the output scalar.
// pass2: grid (6), 128 threads. Reduces 64 split-partials per column group
//        (3 MB scratch, L2-resident), computes cc, block-reduces, atomicAdd.

#define NT              4096
#define NCOL            3072
#define NC4             768          // NCOL / 4
#define SPLITS          64
#define ROWS_PER_SPLIT  64           // NT / SPLITS
#define BLK             128
#define COL_BLOCKS      6            // NC4 / BLK
#define DT_CONST        0.001f
#define EPS_CONST       1e-10f

__device__ float4 g_sx2[SPLITS * NC4];
__device__ float4 g_sy2[SPLITS * NC4];
__device__ float4 g_sxy[SPLITS * NC4];
__device__ float4 g_mx [SPLITS * NC4];

__device__ __forceinline__ void accum(const float4 xv, const float4 yv,
                                      float4& sx2, float4& sy2,
                                      float4& sxy, float4& mx) {
    sx2.x = fmaf(xv.x, xv.x, sx2.x);
    sx2.y = fmaf(xv.y, xv.y, sx2.y);
    sx2.z = fmaf(xv.z, xv.z, sx2.z);
    sx2.w = fmaf(xv.w, xv.w, sx2.w);
    sy2.x = fmaf(yv.x, yv.x, sy2.x);
    sy2.y = fmaf(yv.y, yv.y, sy2.y);
    sy2.z = fmaf(yv.z, yv.z, sy2.z);
    sy2.w = fmaf(yv.w, yv.w, sy2.w);
    sxy.x = fmaf(xv.x, yv.x, sxy.x);
    sxy.y = fmaf(xv.y, yv.y, sxy.y);
    sxy.z = fmaf(xv.z, yv.z, sxy.z);
    sxy.w = fmaf(xv.w, yv.w, sxy.w);
    mx.x = fmaxf(mx.x, fabsf(xv.x));
    mx.y = fmaxf(mx.y, fabsf(xv.y));
    mx.z = fmaxf(mx.z, fabsf(xv.z));
    mx.w = fmaxf(mx.w, fabsf(xv.w));
}

__global__ __launch_bounds__(BLK) void ncc_pass1(const float4* __restrict__ x,
                                                 const float4* __restrict__ y,
                                                 float* __restrict__ out) {
    if (blockIdx.x == 0 && blockIdx.y == 0 && threadIdx.x == 0)
        out[0] = 0.0f;   // pass2 is stream-ordered after pass1: safe.

    const int col4 = blockIdx.x * BLK + threadIdx.x;      // 0..767
    const int row0 = blockIdx.y * ROWS_PER_SPLIT;

    float4 sx2 = make_float4(0.f, 0.f, 0.f, 0.f);
    float4 sy2 = make_float4(0.f, 0.f, 0.f, 0.f);
    float4 sxy = make_float4(0.f, 0.f, 0.f, 0.f);
    float4 mx  = make_float4(0.f, 0.f, 0.f, 0.f);

    const float4* xp = x + (size_t)row0 * NC4 + col4;
    const float4* yp = y + (size_t)row0 * NC4 + col4;

    // Double-buffered, 4 rows per stage: 8 LDG.128 always in flight.
    float4 xa0, xa1, xa2, xa3, ya0, ya1, ya2, ya3;
    xa0 = __ldcs(xp + 0 * NC4);
    xa1 = __ldcs(xp + 1 * NC4);
    xa2 = __ldcs(xp + 2 * NC4);
    xa3 = __ldcs(xp + 3 * NC4);
    ya0 = __ldcs(yp + 0 * NC4);
    ya1 = __ldcs(yp + 1 * NC4);
    ya2 = __ldcs(yp + 2 * NC4);
    ya3 = __ldcs(yp + 3 * NC4);

#pragma unroll
    for (int r = 4; r < ROWS_PER_SPLIT; r += 4) {
        const float4* xn = xp + (size_t)r * NC4;
        const float4* yn = yp + (size_t)r * NC4;
        const float4 xb0 = __ldcs(xn + 0 * NC4);
        const float4 xb1 = __ldcs(xn + 1 * NC4);
        const float4 xb2 = __ldcs(xn + 2 * NC4);
        const float4 xb3 = __ldcs(xn + 3 * NC4);
        const float4 yb0 = __ldcs(yn + 0 * NC4);
        const float4 yb1 = __ldcs(yn + 1 * NC4);
        const float4 yb2 = __ldcs(yn + 2 * NC4);
        const float4 yb3 = __ldcs(yn + 3 * NC4);

        accum(xa0, ya0, sx2, sy2, sxy, mx);
        accum(xa1, ya1, sx2, sy2, sxy, mx);
        accum(xa2, ya2, sx2, sy2, sxy, mx);
        accum(xa3, ya3, sx2, sy2, sxy, mx);

        xa0 = xb0; xa1 = xb1; xa2 = xb2; xa3 = xb3;
        ya0 = yb0; ya1 = yb1; ya2 = yb2; ya3 = yb3;
    }
    accum(xa0, ya0, sx2, sy2, sxy, mx);
    accum(xa1, ya1, sx2, sy2, sxy, mx);
    accum(xa2, ya2, sx2, sy2, sxy, mx);
    accum(xa3, ya3, sx2, sy2, sxy, mx);

    const int o = blockIdx.y * NC4 + col4;
    g_sx2[o] = sx2;
    g_sy2[o] = sy2;
    g_sxy[o] = sxy;
    g_mx [o] = mx;
}

__global__ __launch_bounds__(BLK) void ncc_pass2(float* __restrict__ out) {
    const int col4 = blockIdx.x * BLK + threadIdx.x;      // 0..767

    float4 sx2 = make_float4(0.f, 0.f, 0.f, 0.f);
    float4 sy2 = make_float4(0.f, 0.f, 0.f, 0.f);
    float4 sxy = make_float4(0.f, 0.f, 0.f, 0.f);
    float4 mx  = make_float4(0.f, 0.f, 0.f, 0.f);

#pragma unroll 8
    for (int s = 0; s < SPLITS; s++) {
        const int o = s * NC4 + col4;
        const float4 a = g_sx2[o];
        const float4 b = g_sy2[o];
        const float4 c = g_sxy[o];
        const float4 m = g_mx [o];
        sx2.x += a.x; sx2.y += a.y; sx2.z += a.z; sx2.w += a.w;
        sy2.x += b.x; sy2.y += b.y; sy2.z += b.z; sy2.w += b.w;
        sxy.x += c.x; sxy.y += c.y; sxy.z += c.z; sxy.w += c.w;
        mx.x = fmaxf(mx.x, m.x); mx.y = fmaxf(mx.y, m.y);
        mx.z = fmaxf(mx.z, m.z); mx.w = fmaxf(mx.w, m.w);
    }

    float acc = 0.0f;
    {
        const float ex = DT_CONST * sx2.x + EPS_CONST;
        const float ey = DT_CONST * sy2.x + EPS_CONST;
        if (mx.x > 0.f) acc += sxy.x / sqrtf(ex * ey);
    }
    {
        const float ex = DT_CONST * sx2.y + EPS_CONST;
        const float ey = DT_CONST * sy2.y + EPS_CONST;
        if (mx.y > 0.f) acc += sxy.y / sqrtf(ex * ey);
    }
    {
        const float ex = DT_CONST * sx2.z + EPS_CONST;
        const float ey = DT_CONST * sy2.z + EPS_CONST;
        if (mx.z > 0.f) acc += sxy.z / sqrtf(ex * ey);
    }
    {
        const float ex = DT_CONST * sx2.w + EPS_CONST;
        const float ey = DT_CONST * sy2.w + EPS_CONST;
        if (mx.w > 0.f) acc += sxy.w / sqrtf(ex * ey);
    }

    // warp reduce
#pragma unroll
    for (int off = 16; off > 0; off >>= 1)
        acc += __shfl_down_sync(0xFFFFFFFFu, acc, off);

    __shared__ float warp_sums[BLK / 32];
    const int lane = threadIdx.x & 31;
    const int wid  = threadIdx.x >> 5;
    if (lane == 0) warp_sums[wid] = acc;
    __syncthreads();

    if (wid == 0) {
        float v = (lane < BLK / 32) ? warp_sums[lane] : 0.0f;
#pragma unroll
        for (int off = 2; off > 0; off >>= 1)
            v += __shfl_down_sync(0xFFFFFFFFu, v, off);
        if (lane == 0) atomicAdd(out, v);
    }
}

extern "C" void kernel_launch(void* const* d_in, const int* in_sizes, int n_in,
                              void* d_out, int out_size) {
    const float4* x = (const float4*)d_in[0];
    const float4* y = (const float4*)d_in[1];
    float* out = (float*)d_out;

    ncc_pass1<<<dim3(COL_BLOCKS, SPLITS), BLK>>>(x, y, out);
    ncc_pass2<<<COL_BLOCKS, BLK>>>(out);
}

// round 4
// speedup vs baseline: 2.7439x; 1.7404x over previous
#include <cuda_runtime.h>

// NormalizedCrossCorrelation via Parseval identity:
//   sum_k |X_k|^2 = nt * sum_n x_n^2  =>  Ex = DT * sum(x^2) + EPS
//   cc = sum(x*y) / sqrt(Ex*Ey), masked by max|x|>0, summed over all columns.
//
// x,y: [nt=4096, ncol=3072] row-major (columns contiguous).
// pass1: grid (6, 64), 128 threads. Thread owns one float4 column-group for 64
//        rows, double-buffered loads (8 LDG.128 in flight). Coalesced DRAM
//        streaming; writes per-split partials to 3 MB __device__ scratch (L2).
//        Block (0,0) zeroes the output scalar.
// pass2: 96 blocks x 256 threads = 768 warps; ONE WARP PER col4 group.
//        Each lane loads 2 of the 64 split-partials (8 independent loads),
//        warp-shuffle reduces (sum / max), lane 0 computes cc for its 4
//        columns, block-reduces across 8 warps, one atomicAdd per block.

#define NT              4096
#define NCOL            3072
#define NC4             768          // NCOL / 4
#define SPLITS          64
#define ROWS_PER_SPLIT  64           // NT / SPLITS
#define BLK             128
#define COL_BLOCKS      6            // NC4 / BLK
#define BLK2            256
#define WARPS2          (BLK2 / 32)
#define GRID2           (NC4 / WARPS2)   // 96 blocks
#define DT_CONST        0.001f
#define EPS_CONST       1e-10f

__device__ float4 g_sx2[SPLITS * NC4];
__device__ float4 g_sy2[SPLITS * NC4];
__device__ float4 g_sxy[SPLITS * NC4];
__device__ float4 g_mx [SPLITS * NC4];

__device__ __forceinline__ void accum(const float4 xv, const float4 yv,
                                      float4& sx2, float4& sy2,
                                      float4& sxy, float4& mx) {
    sx2.x = fmaf(xv.x, xv.x, sx2.x);
    sx2.y = fmaf(xv.y, xv.y, sx2.y);
    sx2.z = fmaf(xv.z, xv.z, sx2.z);
    sx2.w = fmaf(xv.w, xv.w, sx2.w);
    sy2.x = fmaf(yv.x, yv.x, sy2.x);
    sy2.y = fmaf(yv.y, yv.y, sy2.y);
    sy2.z = fmaf(yv.z, yv.z, sy2.z);
    sy2.w = fmaf(yv.w, yv.w, sy2.w);
    sxy.x = fmaf(xv.x, yv.x, sxy.x);
    sxy.y = fmaf(xv.y, yv.y, sxy.y);
    sxy.z = fmaf(xv.z, yv.z, sxy.z);
    sxy.w = fmaf(xv.w, yv.w, sxy.w);
    mx.x = fmaxf(mx.x, fabsf(xv.x));
    mx.y = fmaxf(mx.y, fabsf(xv.y));
    mx.z = fmaxf(mx.z, fabsf(xv.z));
    mx.w = fmaxf(mx.w, fabsf(xv.w));
}

__global__ __launch_bounds__(BLK) void ncc_pass1(const float4* __restrict__ x,
                                                 const float4* __restrict__ y,
                                                 float* __restrict__ out) {
    if (blockIdx.x == 0 && blockIdx.y == 0 && threadIdx.x == 0)
        out[0] = 0.0f;   // pass2 is stream-ordered after pass1: safe.

    const int col4 = blockIdx.x * BLK + threadIdx.x;      // 0..767
    const int row0 = blockIdx.y * ROWS_PER_SPLIT;

    float4 sx2 = make_float4(0.f, 0.f, 0.f, 0.f);
    float4 sy2 = make_float4(0.f, 0.f, 0.f, 0.f);
    float4 sxy = make_float4(0.f, 0.f, 0.f, 0.f);
    float4 mx  = make_float4(0.f, 0.f, 0.f, 0.f);

    const float4* xp = x + (size_t)row0 * NC4 + col4;
    const float4* yp = y + (size_t)row0 * NC4 + col4;

    // Double-buffered, 4 rows per stage: 8 LDG.128 always in flight.
    float4 xa0, xa1, xa2, xa3, ya0, ya1, ya2, ya3;
    xa0 = __ldcs(xp + 0 * NC4);
    xa1 = __ldcs(xp + 1 * NC4);
    xa2 = __ldcs(xp + 2 * NC4);
    xa3 = __ldcs(xp + 3 * NC4);
    ya0 = __ldcs(yp + 0 * NC4);
    ya1 = __ldcs(yp + 1 * NC4);
    ya2 = __ldcs(yp + 2 * NC4);
    ya3 = __ldcs(yp + 3 * NC4);

#pragma unroll
    for (int r = 4; r < ROWS_PER_SPLIT; r += 4) {
        const float4* xn = xp + (size_t)r * NC4;
        const float4* yn = yp + (size_t)r * NC4;
        const float4 xb0 = __ldcs(xn + 0 * NC4);
        const float4 xb1 = __ldcs(xn + 1 * NC4);
        const float4 xb2 = __ldcs(xn + 2 * NC4);
        const float4 xb3 = __ldcs(xn + 3 * NC4);
        const float4 yb0 = __ldcs(yn + 0 * NC4);
        const float4 yb1 = __ldcs(yn + 1 * NC4);
        const float4 yb2 = __ldcs(yn + 2 * NC4);
        const float4 yb3 = __ldcs(yn + 3 * NC4);

        accum(xa0, ya0, sx2, sy2, sxy, mx);
        accum(xa1, ya1, sx2, sy2, sxy, mx);
        accum(xa2, ya2, sx2, sy2, sxy, mx);
        accum(xa3, ya3, sx2, sy2, sxy, mx);

        xa0 = xb0; xa1 = xb1; xa2 = xb2; xa3 = xb3;
        ya0 = yb0; ya1 = yb1; ya2 = yb2; ya3 = yb3;
    }
    accum(xa0, ya0, sx2, sy2, sxy, mx);
    accum(xa1, ya1, sx2, sy2, sxy, mx);
    accum(xa2, ya2, sx2, sy2, sxy, mx);
    accum(xa3, ya3, sx2, sy2, sxy, mx);

    const int o = blockIdx.y * NC4 + col4;
    g_sx2[o] = sx2;
    g_sy2[o] = sy2;
    g_sxy[o] = sxy;
    g_mx [o] = mx;
}

__device__ __forceinline__ void wsum4(float4& v) {
#pragma unroll
    for (int off = 16; off > 0; off >>= 1) {
        v.x += __shfl_xor_sync(0xFFFFFFFFu, v.x, off);
        v.y += __shfl_xor_sync(0xFFFFFFFFu, v.y, off);
        v.z += __shfl_xor_sync(0xFFFFFFFFu, v.z, off);
        v.w += __shfl_xor_sync(0xFFFFFFFFu, v.w, off);
    }
}

__device__ __forceinline__ void wmax4(float4& v) {
#pragma unroll
    for (int off = 16; off > 0; off >>= 1) {
        v.x = fmaxf(v.x, __shfl_xor_sync(0xFFFFFFFFu, v.x, off));
        v.y = fmaxf(v.y, __shfl_xor_sync(0xFFFFFFFFu, v.y, off));
        v.z = fmaxf(v.z, __shfl_xor_sync(0xFFFFFFFFu, v.z, off));
        v.w = fmaxf(v.w, __shfl_xor_sync(0xFFFFFFFFu, v.w, off));
    }
}

__global__ __launch_bounds__(BLK2) void ncc_pass2(float* __restrict__ out) {
    const int lane = threadIdx.x & 31;
    const int wid  = threadIdx.x >> 5;
    const int col4 = blockIdx.x * WARPS2 + wid;   // 0..767, one warp per col4

    // Each lane owns 2 of the 64 splits: 8 independent 16B loads.
    const int s0 = lane * 2;
    const int o0 = s0 * NC4 + col4;
    const int o1 = o0 + NC4;                      // (s0+1) * NC4 + col4

    const float4 a0 = g_sx2[o0], a1 = g_sx2[o1];
    const float4 b0 = g_sy2[o0], b1 = g_sy2[o1];
    const float4 c0 = g_sxy[o0], c1 = g_sxy[o1];
    const float4 m0 = g_mx [o0], m1 = g_mx [o1];

    float4 sx2 = make_float4(a0.x + a1.x, a0.y + a1.y, a0.z + a1.z, a0.w + a1.w);
    float4 sy2 = make_float4(b0.x + b1.x, b0.y + b1.y, b0.z + b1.z, b0.w + b1.w);
    float4 sxy = make_float4(c0.x + c1.x, c0.y + c1.y, c0.z + c1.z, c0.w + c1.w);
    float4 mx  = make_float4(fmaxf(m0.x, m1.x), fmaxf(m0.y, m1.y),
                             fmaxf(m0.z, m1.z), fmaxf(m0.w, m1.w));

    wsum4(sx2);
    wsum4(sy2);
    wsum4(sxy);
    wmax4(mx);

    __shared__ float warp_sums[WARPS2];

    if (lane == 0) {
        float acc = 0.0f;
        {
            const float ex = DT_CONST * sx2.x + EPS_CONST;
            const float ey = DT_CONST * sy2.x + EPS_CONST;
            if (mx.x > 0.f) acc += sxy.x / sqrtf(ex * ey);
        }
        {
            const float ex = DT_CONST * sx2.y + EPS_CONST;
            const float ey = DT_CONST * sy2.y + EPS_CONST;
            if (mx.y > 0.f) acc += sxy.y / sqrtf(ex * ey);
        }
        {
            const float ex = DT_CONST * sx2.z + EPS_CONST;
            const float ey = DT_CONST * sy2.z + EPS_CONST;
            if (mx.z > 0.f) acc += sxy.z / sqrtf(ex * ey);
        }
        {
            const float ex = DT_CONST * sx2.w + EPS_CONST;
            const float ey = DT_CONST * sy2.w + EPS_CONST;
            if (mx.w > 0.f) acc += sxy.w / sqrtf(ex * ey);
        }
        warp_sums[wid] = acc;
    }
    __syncthreads();

    if (threadIdx.x == 0) {
        float v = 0.0f;
#pragma unroll
        for (int w = 0; w < WARPS2; w++) v += warp_sums[w];
        atomicAdd(out, v);
    }
}

extern "C" void kernel_launch(void* const* d_in, const int* in_sizes, int n_in,
                              void* d_out, int out_size) {
    const float4* x = (const float4*)d_in[0];
    const float4* y = (const float4*)d_in[1];
    float* out = (float*)d_out;

    ncc_pass1<<<dim3(COL_BLOCKS, SPLITS), BLK>>>(x, y, out);
    ncc_pass2<<<GRID2, BLK2>>>(out);
}

// round 8
// speedup vs baseline: 4.3933x; 1.6011x over previous
#include <cuda_runtime.h>

// NormalizedCrossCorrelation via Parseval identity:
//   sum_k |X_k|^2 = nt * sum_n x_n^2  =>  Ex = DT * sum(x^2) + EPS
//   cc = sum(x*y) / sqrt(Ex*Ey), masked by max|x|>0, summed over all columns.
//
// x,y: [nt=4096, ncol=3072] row-major (columns contiguous).
//
// pass1: grid (6, 32), 512 threads = 4 time-slices x 128 col4 lanes.
//        Each thread streams 32 rows (double-buffered, 8 LDG.128 in flight),
//        then slices 1-3 spill stats to smem and slice 0 folds them, writing
//        ONE partial per (block.y, col4): 32 splits, 1.5 MB scratch (L2).
// pass2: 96 blocks x 256 threads, one warp per col4 group. Lane = split index
//        (exactly 32 splits), warp-shuffle reduce, lane 0 computes cc,
//        block-reduces 8 warps, one atomicAdd per block.

#define NT              4096
#define NCOL            3072
#define NC4             768          // NCOL / 4
#define SPLITS          32           // = pass1 grid.y
#define SLICES          4
#define COLS_PER_BLK    128
#define ROWS_PER_THREAD 32           // NT / SPLITS / SLICES
#define BLK1            (SLICES * COLS_PER_BLK)   // 512
#define COL_BLOCKS      6            // NC4 / COLS_PER_BLK
#define BLK2            256
#define WARPS2          (BLK2 / 32)
#define GRID2           (NC4 / WARPS2)   // 96
#define DT_CONST        0.001f
#define EPS_CONST       1e-10f

__device__ float4 g_sx2[SPLITS * NC4];
__device__ float4 g_sy2[SPLITS * NC4];
__device__ float4 g_sxy[SPLITS * NC4];
__device__ float4 g_mx [SPLITS * NC4];

__device__ __forceinline__ void accum(const float4 xv, const float4 yv,
                                      float4& sx2, float4& sy2,
                                      float4& sxy, float4& mx) {
    sx2.x = fmaf(xv.x, xv.x, sx2.x);
    sx2.y = fmaf(xv.y, xv.y, sx2.y);
    sx2.z = fmaf(xv.z, xv.z, sx2.z);
    sx2.w = fmaf(xv.w, xv.w, sx2.w);
    sy2.x = fmaf(yv.x, yv.x, sy2.x);
    sy2.y = fmaf(yv.y, yv.y, sy2.y);
    sy2.z = fmaf(yv.z, yv.z, sy2.z);
    sy2.w = fmaf(yv.w, yv.w, sy2.w);
    sxy.x = fmaf(xv.x, yv.x, sxy.x);
    sxy.y = fmaf(xv.y, yv.y, sxy.y);
    sxy.z = fmaf(xv.z, yv.z, sxy.z);
    sxy.w = fmaf(xv.w, yv.w, sxy.w);
    mx.x = fmaxf(mx.x, fabsf(xv.x));
    mx.y = fmaxf(mx.y, fabsf(xv.y));
    mx.z = fmaxf(mx.z, fabsf(xv.z));
    mx.w = fmaxf(mx.w, fabsf(xv.w));
}

__global__ __launch_bounds__(BLK1, 2) void ncc_pass1(const float4* __restrict__ x,
                                                     const float4* __restrict__ y,
                                                     float* __restrict__ out) {
    if (blockIdx.x == 0 && blockIdx.y == 0 && threadIdx.x == 0)
        out[0] = 0.0f;   // pass2 is stream-ordered after pass1: safe.

    const int c     = threadIdx.x & (COLS_PER_BLK - 1);   // 0..127
    const int slice = threadIdx.x >> 7;                   // 0..3
    const int col4  = blockIdx.x * COLS_PER_BLK + c;      // 0..767
    const int row0  = blockIdx.y * (SLICES * ROWS_PER_THREAD) + slice * ROWS_PER_THREAD;

    float4 sx2 = make_float4(0.f, 0.f, 0.f, 0.f);
    float4 sy2 = make_float4(0.f, 0.f, 0.f, 0.f);
    float4 sxy = make_float4(0.f, 0.f, 0.f, 0.f);
    float4 mx  = make_float4(0.f, 0.f, 0.f, 0.f);

    const float4* xp = x + (size_t)row0 * NC4 + col4;
    const float4* yp = y + (size_t)row0 * NC4 + col4;

    // Double-buffered, 4 rows per stage: 8 LDG.128 always in flight.
    float4 xa0, xa1, xa2, xa3, ya0, ya1, ya2, ya3;
    xa0 = __ldcs(xp + 0 * NC4);
    xa1 = __ldcs(xp + 1 * NC4);
    xa2 = __ldcs(xp + 2 * NC4);
    xa3 = __ldcs(xp + 3 * NC4);
    ya0 = __ldcs(yp + 0 * NC4);
    ya1 = __ldcs(yp + 1 * NC4);
    ya2 = __ldcs(yp + 2 * NC4);
    ya3 = __ldcs(yp + 3 * NC4);

#pragma unroll
    for (int r = 4; r < ROWS_PER_THREAD; r += 4) {
        const float4* xn = xp + (size_t)r * NC4;
        const float4* yn = yp + (size_t)r * NC4;
        const float4 xb0 = __ldcs(xn + 0 * NC4);
        const float4 xb1 = __ldcs(xn + 1 * NC4);
        const float4 xb2 = __ldcs(xn + 2 * NC4);
        const float4 xb3 = __ldcs(xn + 3 * NC4);
        const float4 yb0 = __ldcs(yn + 0 * NC4);
        const float4 yb1 = __ldcs(yn + 1 * NC4);
        const float4 yb2 = __ldcs(yn + 2 * NC4);
        const float4 yb3 = __ldcs(yn + 3 * NC4);

        accum(xa0, ya0, sx2, sy2, sxy, mx);
        accum(xa1, ya1, sx2, sy2, sxy, mx);
        accum(xa2, ya2, sx2, sy2, sxy, mx);
        accum(xa3, ya3, sx2, sy2, sxy, mx);

        xa0 = xb0; xa1 = xb1; xa2 = xb2; xa3 = xb3;
        ya0 = yb0; ya1 = yb1; ya2 = yb2; ya3 = yb3;
    }
    accum(xa0, ya0, sx2, sy2, sxy, mx);
    accum(xa1, ya1, sx2, sy2, sxy, mx);
    accum(xa2, ya2, sx2, sy2, sxy, mx);
    accum(xa3, ya3, sx2, sy2, sxy, mx);

    // Intra-block reduction across the 4 time slices.
    // 4 separate float4 arrays: consecutive lanes -> consecutive 16B, conflict-free.
    __shared__ float4 r_sx2[SLICES - 1][COLS_PER_BLK];
    __shared__ float4 r_sy2[SLICES - 1][COLS_PER_BLK];
    __shared__ float4 r_sxy[SLICES - 1][COLS_PER_BLK];
    __shared__ float4 r_mx [SLICES - 1][COLS_PER_BLK];

    if (slice > 0) {
        r_sx2[slice - 1][c] = sx2;
        r_sy2[slice - 1][c] = sy2;
        r_sxy[slice - 1][c] = sxy;
        r_mx [slice - 1][c] = mx;
    }
    __syncthreads();

    if (slice == 0) {
#pragma unroll
        for (int s = 0; s < SLICES - 1; s++) {
            const float4 a = r_sx2[s][c];
            const float4 b = r_sy2[s][c];
            const float4 d = r_sxy[s][c];
            const float4 m = r_mx [s][c];
            sx2.x += a.x; sx2.y += a.y; sx2.z += a.z; sx2.w += a.w;
            sy2.x += b.x; sy2.y += b.y; sy2.z += b.z; sy2.w += b.w;
            sxy.x += d.x; sxy.y += d.y; sxy.z += d.z; sxy.w += d.w;
            mx.x = fmaxf(mx.x, m.x); mx.y = fmaxf(mx.y, m.y);
            mx.z = fmaxf(mx.z, m.z); mx.w = fmaxf(mx.w, m.w);
        }
        const int o = blockIdx.y * NC4 + col4;
        g_sx2[o] = sx2;
        g_sy2[o] = sy2;
        g_sxy[o] = sxy;
        g_mx [o] = mx;
    }
}

__device__ __forceinline__ void wsum4(float4& v) {
#pragma unroll
    for (int off = 16; off > 0; off >>= 1) {
        v.x += __shfl_xor_sync(0xFFFFFFFFu, v.x, off);
        v.y += __shfl_xor_sync(0xFFFFFFFFu, v.y, off);
        v.z += __shfl_xor_sync(0xFFFFFFFFu, v.z, off);
        v.w += __shfl_xor_sync(0xFFFFFFFFu, v.w, off);
    }
}

__device__ __forceinline__ void wmax4(float4& v) {
#pragma unroll
    for (int off = 16; off > 0; off >>= 1) {
        v.x = fmaxf(v.x, __shfl_xor_sync(0xFFFFFFFFu, v.x, off));
        v.y = fmaxf(v.y, __shfl_xor_sync(0xFFFFFFFFu, v.y, off));
        v.z = fmaxf(v.z, __shfl_xor_sync(0xFFFFFFFFu, v.z, off));
        v.w = fmaxf(v.w, __shfl_xor_sync(0xFFFFFFFFu, v.w, off));
    }
}

__global__ __launch_bounds__(BLK2) void ncc_pass2(float* __restrict__ out) {
    const int lane = threadIdx.x & 31;
    const int wid  = threadIdx.x >> 5;
    const int col4 = blockIdx.x * WARPS2 + wid;   // 0..767, one warp per col4

    // Lane = split index: exactly SPLITS==32 partials per column group.
    const int o = lane * NC4 + col4;

    float4 sx2 = g_sx2[o];
    float4 sy2 = g_sy2[o];
    float4 sxy = g_sxy[o];
    float4 mx  = g_mx [o];

    wsum4(sx2);
    wsum4(sy2);
    wsum4(sxy);
    wmax4(mx);

    __shared__ float warp_sums[WARPS2];

    if (lane == 0) {
        float acc = 0.0f;
        {
            const float ex = DT_CONST * sx2.x + EPS_CONST;
            const float ey = DT_CONST * sy2.x + EPS_CONST;
            if (mx.x > 0.f) acc += sxy.x / sqrtf(ex * ey);
        }
        {
            const float ex = DT_CONST * sx2.y + EPS_CONST;
            const float ey = DT_CONST * sy2.y + EPS_CONST;
            if (mx.y > 0.f) acc += sxy.y / sqrtf(ex * ey);
        }
        {
            const float ex = DT_CONST * sx2.z + EPS_CONST;
            const float ey = DT_CONST * sy2.z + EPS_CONST;
            if (mx.z > 0.f) acc += sxy.z / sqrtf(ex * ey);
        }
        {
            const float ex = DT_CONST * sx2.w + EPS_CONST;
            const float ey = DT_CONST * sy2.w + EPS_CONST;
            if (mx.w > 0.f) acc += sxy.w / sqrtf(ex * ey);
        }
        warp_sums[wid] = acc;
    }
    __syncthreads();

    if (threadIdx.x == 0) {
        float v = 0.0f;
#pragma unroll
        for (int w = 0; w < WARPS2; w++) v += warp_sums[w];
        atomicAdd(out, v);
    }
}

extern "C" void kernel_launch(void* const* d_in, const int* in_sizes, int n_in,
                              void* d_out, int out_size) {
    const float4* x = (const float4*)d_in[0];
    const float4* y = (const float4*)d_in[1];
    float* out = (float*)d_out;

    ncc_pass1<<<dim3(COL_BLOCKS, SPLITS), BLK1>>>(x, y, out);
    ncc_pass2<<<GRID2, BLK2>>>(out);
}